// round 7
// baseline (speedup 1.0000x reference)
#include <cuda_runtime.h>

#define E_TOTAL 20000
#define FDIM 17
#define HDIM 32
#define TILE_E 128
#define LN_EPS 1e-5f

__device__ float g_h[E_TOTAL * HDIM];

// ---------- packed fp32x2 helpers (Blackwell dual-FP32) ----------
__device__ __forceinline__ unsigned long long pk2(float x, float y) {
    unsigned long long r;
    asm("mov.b64 %0, {%1, %2};" : "=l"(r) : "f"(x), "f"(y));
    return r;
}
__device__ __forceinline__ void upk2(unsigned long long v, float& x, float& y) {
    asm("mov.b64 {%0, %1}, %2;" : "=f"(x), "=f"(y) : "l"(v));
}
__device__ __forceinline__ void fma2(unsigned long long& d,
                                     unsigned long long a, unsigned long long b) {
    asm("fma.rn.f32x2 %0, %1, %2, %0;" : "+l"(d) : "l"(a), "l"(b));
}
__device__ __forceinline__ void stcs(float* p, float v) {
    asm volatile("st.global.cs.f32 [%0], %1;" :: "l"(p), "f"(v) : "memory");
}

// ---------------------------------------------------------------------------
// Kernel 1: radial MLP  f[E,17] -> h[E,32]
// 256 threads = 8 warps; each warp processes 4 edges (more parallelism,
// shorter serial LayerNorm chains). Weights staged in smem.
// ---------------------------------------------------------------------------
__global__ __launch_bounds__(256) void mlp_kernel(
    const float* __restrict__ f,
    const float* __restrict__ w1, const float* __restrict__ b1,
    const float* __restrict__ g1, const float* __restrict__ be1,
    const float* __restrict__ w2, const float* __restrict__ b2,
    const float* __restrict__ g2, const float* __restrict__ be2)
{
    const int tid  = threadIdx.x;
    const int warp = tid >> 5;
    const int lane = tid & 31;

    __shared__ float w1s[32 * FDIM];      // 17 odd => conflict-free
    __shared__ float w2s[32 * 33];        // padded
    __shared__ float sf[8][FDIM];
    __shared__ float sh[8][HDIM];

    for (int i = tid; i < 32 * FDIM; i += 256) w1s[i] = w1[i];
    for (int i = tid; i < 32 * 32;  i += 256) w2s[(i >> 5) * 33 + (i & 31)] = w2[i];
    __syncthreads();

    const float bb1 = b1[lane], gg1 = g1[lane], bbe1 = be1[lane];
    const float bb2 = b2[lane], gg2 = g2[lane], bbe2 = be2[lane];

    const int ebase = blockIdx.x * 32 + warp * 4;

    #pragma unroll 1
    for (int it = 0; it < 4; it++) {
        const int e = ebase + it;
        if (e >= E_TOTAL) break;

        if (lane < FDIM) sf[warp][lane] = f[e * FDIM + lane];
        __syncwarp();

        float acc = bb1;
        #pragma unroll
        for (int j = 0; j < FDIM; j++)
            acc = fmaf(sf[warp][j], w1s[lane * FDIM + j], acc);

        float m = acc;
        #pragma unroll
        for (int o = 16; o > 0; o >>= 1) m += __shfl_xor_sync(0xffffffffu, m, o);
        m *= (1.0f / 32.0f);
        float d = acc - m;
        float v = d * d;
        #pragma unroll
        for (int o = 16; o > 0; o >>= 1) v += __shfl_xor_sync(0xffffffffu, v, o);
        v *= (1.0f / 32.0f);
        float y = fmaxf(fmaf(d * rsqrtf(v + LN_EPS), gg1, bbe1), 0.0f);

        sh[warp][lane] = y;
        __syncwarp();

        float acc2 = bb2;
        #pragma unroll
        for (int k = 0; k < HDIM; k++)
            acc2 = fmaf(sh[warp][k], w2s[lane * 33 + k], acc2);

        float m2 = acc2;
        #pragma unroll
        for (int o = 16; o > 0; o >>= 1) m2 += __shfl_xor_sync(0xffffffffu, m2, o);
        m2 *= (1.0f / 32.0f);
        float d2 = acc2 - m2;
        float v2 = d2 * d2;
        #pragma unroll
        for (int o = 16; o > 0; o >>= 1) v2 += __shfl_xor_sync(0xffffffffu, v2, o);
        v2 *= (1.0f / 32.0f);
        float y2 = fmaxf(fmaf(d2 * rsqrtf(v2 + LN_EPS), gg2, bbe2), 0.0f);

        g_h[e * HDIM + lane] = y2;
        __syncwarp();
    }
}

// ---------------------------------------------------------------------------
// Kernel 2: fused r = h @ w3^T + b3, einsum with basis, direct write.
// Grid (32 co, 157 tiles); block 128 = 4 warps, lane = ci.
// Main loop: f32x2 FMA with register-resident w3 slice.
// Epilogue: streaming float4 consumption of basis into 9 accumulators,
// 9 direct st.global.cs (evict-first: write-once data, spare L2).
// ---------------------------------------------------------------------------
__global__ __launch_bounds__(128, 4) void conv_kernel(
    const float* __restrict__ basis,
    const float* __restrict__ w3,
    const float* __restrict__ b3,
    float* __restrict__ out)
{
    const int co    = blockIdx.x;
    const int ebase = blockIdx.y * TILE_E;
    const int tid   = threadIdx.x;
    const int ci    = tid & 31;
    const int warp  = tid >> 5;

    __shared__ float w_s[96 * 36];
    __shared__ float h_s[TILE_E * HDIM];
    __shared__ float B_s[TILE_E * 28];      // stride 28 (112B, 16B-aligned rows)

    // --- stage w3 slice for this co (contiguous rows) ---
    {
        const float4* src = (const float4*)(w3 + (size_t)co * 96 * 32);
        #pragma unroll
        for (int g = tid; g < 768; g += 128) {
            int row = g >> 3, qi = g & 7;
            *(float4*)&w_s[row * 36 + qi * 4] = src[g];
        }
    }
    const int nE = (E_TOTAL - ebase < TILE_E) ? (E_TOTAL - ebase) : TILE_E;
    // --- stage h tile ---
    {
        const float4* src = (const float4*)(g_h + (size_t)ebase * HDIM);
        const int nf4 = (nE * HDIM) >> 2;
        for (int g = tid; g < nf4; g += 128)
            *(float4*)&h_s[g * 4] = src[g];
    }
    // --- stage basis tile (27 -> stride 28) ---
    {
        const float* src = basis + (size_t)ebase * 27;
        const int n = nE * 27;
        for (int g = tid; g < n; g += 128) {
            int el = g / 27, j = g - el * 27;
            B_s[el * 28 + j] = src[g];
        }
    }
    __syncthreads();

    // --- per-thread register copy of its 3 w3 rows, packed f32x2 ---
    unsigned long long wpk[3][16];
    #pragma unroll
    for (int ff = 0; ff < 3; ff++) {
        const float* wr = &w_s[(ci * 3 + ff) * 36];
        #pragma unroll
        for (int q = 0; q < 8; q++) {
            float4 t = *(const float4*)&wr[q * 4];
            wpk[ff][2 * q + 0] = pk2(t.x, t.y);
            wpk[ff][2 * q + 1] = pk2(t.z, t.w);
        }
    }
    const int ibase = (co * 32 + ci) * 3;
    const float bias0 = b3[ibase + 0];
    const float bias1 = b3[ibase + 1];
    const float bias2 = b3[ibase + 2];

    #pragma unroll 1
    for (int el = warp * 32; el < (warp + 1) * 32; el++) {
        if (el >= nE) break;                      // warp-uniform

        unsigned long long a0 = pk2(bias0, 0.0f);
        unsigned long long a1 = pk2(bias1, 0.0f);
        unsigned long long a2 = pk2(bias2, 0.0f);

        const float* hp = &h_s[el * HDIM];
        #pragma unroll
        for (int q = 0; q < 8; q++) {
            float4 hv = *(const float4*)&hp[q * 4];   // LDS.128 broadcast
            unsigned long long h01 = pk2(hv.x, hv.y);
            unsigned long long h23 = pk2(hv.z, hv.w);
            fma2(a0, h01, wpk[0][2 * q]);  fma2(a0, h23, wpk[0][2 * q + 1]);
            fma2(a1, h01, wpk[1][2 * q]);  fma2(a1, h23, wpk[1][2 * q + 1]);
            fma2(a2, h01, wpk[2][2 * q]);  fma2(a2, h23, wpk[2][2 * q + 1]);
        }
        float r0, r0b, r1, r1b, r2, r2b;
        upk2(a0, r0, r0b);  upk2(a1, r1, r1b);  upk2(a2, r2, r2b);
        r0 += r0b;  r1 += r1b;  r2 += r2b;

        // --- streaming epilogue: consume basis float4s immediately ---
        const float4* Bp4 = (const float4*)&B_s[el * 28];
        float o0, o1, o2, o3, o4, o5, o6, o7, o8;
        {
            float4 a = Bp4[0];                                  // m 0..3
            o0 = fmaf(r2, a.z, fmaf(r1, a.y, r0 * a.x));
            o1 = r0 * a.w;
            float4 b = Bp4[1];                                  // m 4..7
            o1 = fmaf(r2, b.y, fmaf(r1, b.x, o1));
            o2 = fmaf(r1, b.w, r0 * b.z);
            float4 c = Bp4[2];                                  // m 8..11
            o2 = fmaf(r2, c.x, o2);
            o3 = fmaf(r2, c.w, fmaf(r1, c.z, r0 * c.y));
            float4 d = Bp4[3];                                  // m 12..15
            o4 = fmaf(r2, d.z, fmaf(r1, d.y, r0 * d.x));
            o5 = r0 * d.w;
            float4 e4 = Bp4[4];                                 // m 16..19
            o5 = fmaf(r2, e4.y, fmaf(r1, e4.x, o5));
            o6 = fmaf(r1, e4.w, r0 * e4.z);
            float4 f4 = Bp4[5];                                 // m 20..23
            o6 = fmaf(r2, f4.x, o6);
            o7 = fmaf(r2, f4.w, fmaf(r1, f4.z, r0 * f4.y));
            float4 g4 = Bp4[6];                                 // m 24..26 (+pad)
            o8 = fmaf(r2, g4.z, fmaf(r1, g4.y, r0 * g4.x));
        }

        float* op = out + (size_t)(ebase + el) * 9216 + (size_t)(co * 3) * 96 + ci * 3;
        stcs(op + 0,   o0);  stcs(op + 1,   o1);  stcs(op + 2,   o2);
        stcs(op + 96,  o3);  stcs(op + 97,  o4);  stcs(op + 98,  o5);
        stcs(op + 192, o6);  stcs(op + 193, o7);  stcs(op + 194, o8);
    }
}

// ---------------------------------------------------------------------------
extern "C" void kernel_launch(void* const* d_in, const int* in_sizes, int n_in,
                              void* d_out, int out_size)
{
    const float* f     = (const float*)d_in[0];
    const float* basis = (const float*)d_in[1];
    const float* w1    = (const float*)d_in[2];
    const float* b1    = (const float*)d_in[3];
    const float* g1    = (const float*)d_in[4];
    const float* be1   = (const float*)d_in[5];
    const float* w2    = (const float*)d_in[6];
    const float* b2    = (const float*)d_in[7];
    const float* g2    = (const float*)d_in[8];
    const float* be2   = (const float*)d_in[9];
    const float* w3    = (const float*)d_in[10];
    const float* b3    = (const float*)d_in[11];
    float* out = (float*)d_out;

    mlp_kernel<<<(E_TOTAL + 31) / 32, 256>>>(f, w1, b1, g1, be1, w2, b2, g2, be2);

    dim3 grid(32, (E_TOTAL + TILE_E - 1) / TILE_E);
    conv_kernel<<<grid, 128>>>(basis, w3, b3, out);
}

// round 10
// speedup vs baseline: 1.0918x; 1.0918x over previous
#include <cuda_runtime.h>

#define E_TOTAL 20000
#define FDIM 17
#define HDIM 32
#define TILE_E 64
#define LN_EPS 1e-5f

__device__ float g_h[E_TOTAL * HDIM];

// ---------- packed fp32x2 helpers (Blackwell dual-FP32) ----------
__device__ __forceinline__ unsigned long long pk2(float x, float y) {
    unsigned long long r;
    asm("mov.b64 %0, {%1, %2};" : "=l"(r) : "f"(x), "f"(y));
    return r;
}
__device__ __forceinline__ void upk2(unsigned long long v, float& x, float& y) {
    asm("mov.b64 {%0, %1}, %2;" : "=f"(x), "=f"(y) : "l"(v));
}
__device__ __forceinline__ void fma2(unsigned long long& d,
                                     unsigned long long a, unsigned long long b) {
    asm("fma.rn.f32x2 %0, %1, %2, %0;" : "+l"(d) : "l"(a), "l"(b));
}
__device__ __forceinline__ unsigned smem_u32(const void* p) {
    unsigned a;
    asm("{ .reg .u64 t; cvta.to.shared.u64 t, %1; cvt.u32.u64 %0, t; }" : "=r"(a) : "l"(p));
    return a;
}

// ---------------------------------------------------------------------------
// Kernel 1: radial MLP  f[E,17] -> h[E,32]   (4 edges per warp)
// ---------------------------------------------------------------------------
__global__ __launch_bounds__(256) void mlp_kernel(
    const float* __restrict__ f,
    const float* __restrict__ w1, const float* __restrict__ b1,
    const float* __restrict__ g1, const float* __restrict__ be1,
    const float* __restrict__ w2, const float* __restrict__ b2,
    const float* __restrict__ g2, const float* __restrict__ be2)
{
    const int tid  = threadIdx.x;
    const int warp = tid >> 5;
    const int lane = tid & 31;

    __shared__ float w1s[32 * FDIM];
    __shared__ float w2s[32 * 33];
    __shared__ float sf[8][FDIM];
    __shared__ float sh[8][HDIM];

    for (int i = tid; i < 32 * FDIM; i += 256) w1s[i] = w1[i];
    for (int i = tid; i < 32 * 32;  i += 256) w2s[(i >> 5) * 33 + (i & 31)] = w2[i];
    __syncthreads();

    const float bb1 = b1[lane], gg1 = g1[lane], bbe1 = be1[lane];
    const float bb2 = b2[lane], gg2 = g2[lane], bbe2 = be2[lane];

    const int ebase = blockIdx.x * 32 + warp * 4;

    #pragma unroll 1
    for (int it = 0; it < 4; it++) {
        const int e = ebase + it;
        if (e >= E_TOTAL) break;

        if (lane < FDIM) sf[warp][lane] = f[e * FDIM + lane];
        __syncwarp();

        float acc = bb1;
        #pragma unroll
        for (int j = 0; j < FDIM; j++)
            acc = fmaf(sf[warp][j], w1s[lane * FDIM + j], acc);

        float m = acc;
        #pragma unroll
        for (int o = 16; o > 0; o >>= 1) m += __shfl_xor_sync(0xffffffffu, m, o);
        m *= (1.0f / 32.0f);
        float d = acc - m;
        float v = d * d;
        #pragma unroll
        for (int o = 16; o > 0; o >>= 1) v += __shfl_xor_sync(0xffffffffu, v, o);
        v *= (1.0f / 32.0f);
        float y = fmaxf(fmaf(d * rsqrtf(v + LN_EPS), gg1, bbe1), 0.0f);

        sh[warp][lane] = y;
        __syncwarp();

        float acc2 = bb2;
        #pragma unroll
        for (int k = 0; k < HDIM; k++)
            acc2 = fmaf(sh[warp][k], w2s[lane * 33 + k], acc2);

        float m2 = acc2;
        #pragma unroll
        for (int o = 16; o > 0; o >>= 1) m2 += __shfl_xor_sync(0xffffffffu, m2, o);
        m2 *= (1.0f / 32.0f);
        float d2 = acc2 - m2;
        float v2 = d2 * d2;
        #pragma unroll
        for (int o = 16; o > 0; o >>= 1) v2 += __shfl_xor_sync(0xffffffffu, v2, o);
        v2 *= (1.0f / 32.0f);
        float y2 = fmaxf(fmaf(d2 * rsqrtf(v2 + LN_EPS), gg2, bbe2), 0.0f);

        g_h[e * HDIM + lane] = y2;
        __syncwarp();
    }
}

// ---------------------------------------------------------------------------
// Kernel 2: fused r = h @ w3^T + b3, einsum, chunked async-bulk stores.
// Grid (32 co, 313 tiles of 64 edges); block 128 = 4 warps, lane = ci.
// Per warp: 16 edges in 4 chunks of 4, double-buffered staging.
// Per edge: 9 conflict-free STS (9 wf, vs 27 wf strided STG).
// Per chunk: 1 fence + 1 syncwarp + lane0: 4x cp.async.bulk (1152B, proven
// correct in R6) + 1 commit. wait_group.read 1 gates buffer reuse.
// ---------------------------------------------------------------------------
__global__ __launch_bounds__(128, 4) void conv_kernel(
    const float* __restrict__ basis,
    const float* __restrict__ w3,
    const float* __restrict__ b3,
    float* __restrict__ out)
{
    const int co    = blockIdx.x;
    const int ebase = blockIdx.y * TILE_E;
    const int tid   = threadIdx.x;
    const int ci    = tid & 31;
    const int warp  = tid >> 5;

    __shared__ float h_s[TILE_E * HDIM];                 // 8 KB
    __shared__ float B_s[TILE_E * 28];                   // 7 KB
    __shared__ __align__(16) float pool[4 * 2 * 1152];   // 36.9 KB (w_s unioned)
    float* const w_s = pool;                             // [96][36], dead early

    // --- stage w3 slice for this co (contiguous rows) ---
    {
        const float4* src = (const float4*)(w3 + (size_t)co * 96 * 32);
        #pragma unroll
        for (int g = tid; g < 768; g += 128) {
            int row = g >> 3, qi = g & 7;
            *(float4*)&w_s[row * 36 + qi * 4] = src[g];
        }
    }
    const int nE = (E_TOTAL - ebase < TILE_E) ? (E_TOTAL - ebase) : TILE_E;
    // --- stage h tile ---
    {
        const float4* src = (const float4*)(g_h + (size_t)ebase * HDIM);
        const int nf4 = (nE * HDIM) >> 2;
        for (int g = tid; g < nf4; g += 128)
            *(float4*)&h_s[g * 4] = src[g];
    }
    // --- stage basis tile (27 -> stride 28) ---
    {
        const float* src = basis + (size_t)ebase * 27;
        const int n = nE * 27;
        for (int g = tid; g < n; g += 128) {
            int el = g / 27, j = g - el * 27;
            B_s[el * 28 + j] = src[g];
        }
    }
    __syncthreads();

    // --- per-thread register copy of its 3 w3 rows, packed f32x2 ---
    unsigned long long wpk[3][16];
    #pragma unroll
    for (int ff = 0; ff < 3; ff++) {
        const float* wr = &w_s[(ci * 3 + ff) * 36];
        #pragma unroll
        for (int q = 0; q < 8; q++) {
            float4 t = *(const float4*)&wr[q * 4];
            wpk[ff][2 * q + 0] = pk2(t.x, t.y);
            wpk[ff][2 * q + 1] = pk2(t.z, t.w);
        }
    }
    const int ibase = (co * 32 + ci) * 3;
    const float bias0 = b3[ibase + 0];
    const float bias1 = b3[ibase + 1];
    const float bias2 = b3[ibase + 2];
    __syncthreads();                      // w_s dead; staging may begin

    float* const buf0 = pool + warp * 2304;          // double buffer
    float* const buf1 = buf0 + 1152;

    #pragma unroll 1
    for (int c = 0; c < 4; c++) {
        const int el0 = warp * 16 + c * 4;
        if (el0 >= nE) break;             // chunks are full-or-empty (nE % 16 == 0)

        float* const buf = (c & 1) ? buf1 : buf0;

        if (c >= 2) {                     // buffer reused from chunk c-2
            if (ci == 0)
                asm volatile("cp.async.bulk.wait_group.read 1;" ::: "memory");
            __syncwarp();
        }

        #pragma unroll 1
        for (int elc = 0; elc < 4; elc++) {
            const int el = el0 + elc;

            unsigned long long a0 = pk2(bias0, 0.0f);
            unsigned long long a1 = pk2(bias1, 0.0f);
            unsigned long long a2 = pk2(bias2, 0.0f);

            const float* hp = &h_s[el * HDIM];
            #pragma unroll
            for (int q = 0; q < 8; q++) {
                float4 hv = *(const float4*)&hp[q * 4];   // LDS.128 broadcast
                unsigned long long h01 = pk2(hv.x, hv.y);
                unsigned long long h23 = pk2(hv.z, hv.w);
                fma2(a0, h01, wpk[0][2 * q]);  fma2(a0, h23, wpk[0][2 * q + 1]);
                fma2(a1, h01, wpk[1][2 * q]);  fma2(a1, h23, wpk[1][2 * q + 1]);
                fma2(a2, h01, wpk[2][2 * q]);  fma2(a2, h23, wpk[2][2 * q + 1]);
            }
            float r0, r0b, r1, r1b, r2, r2b;
            upk2(a0, r0, r0b);  upk2(a1, r1, r1b);  upk2(a2, r2, r2b);
            r0 += r0b;  r1 += r1b;  r2 += r2b;

            // --- streaming einsum epilogue -> 9 conflict-free STS ---
            const float4* Bp4 = (const float4*)&B_s[el * 28];
            float* bw = buf + elc * 288;
            {
                float4 a = Bp4[0];
                bw[3 * ci + 0] = fmaf(r2, a.z, fmaf(r1, a.y, r0 * a.x));
                float o1p = r0 * a.w;
                float4 b = Bp4[1];
                bw[3 * ci + 1] = fmaf(r2, b.y, fmaf(r1, b.x, o1p));
                float o2p = fmaf(r1, b.w, r0 * b.z);
                float4 cc = Bp4[2];
                bw[3 * ci + 2] = fmaf(r2, cc.x, o2p);
                bw[96 + 3 * ci + 0] = fmaf(r2, cc.w, fmaf(r1, cc.z, r0 * cc.y));
                float4 d = Bp4[3];
                bw[96 + 3 * ci + 1] = fmaf(r2, d.z, fmaf(r1, d.y, r0 * d.x));
                float o5p = r0 * d.w;
                float4 e4 = Bp4[4];
                bw[96 + 3 * ci + 2] = fmaf(r2, e4.y, fmaf(r1, e4.x, o5p));
                float o6p = fmaf(r1, e4.w, r0 * e4.z);
                float4 f4 = Bp4[5];
                bw[192 + 3 * ci + 0] = fmaf(r2, f4.x, o6p);
                bw[192 + 3 * ci + 1] = fmaf(r2, f4.w, fmaf(r1, f4.z, r0 * f4.y));
                float4 g4 = Bp4[6];
                bw[192 + 3 * ci + 2] = fmaf(r2, g4.z, fmaf(r1, g4.y, r0 * g4.x));
            }
        }

        asm volatile("fence.proxy.async.shared::cta;" ::: "memory");
        __syncwarp();

        if (ci == 0) {
            const unsigned sb = smem_u32(buf);
            #pragma unroll
            for (int elc = 0; elc < 4; elc++) {
                const float* dst = out + (size_t)(ebase + el0 + elc) * 9216
                                       + (size_t)co * 288;
                asm volatile(
                    "cp.async.bulk.global.shared::cta.bulk_group [%0], [%1], %2;"
                    :: "l"(dst), "r"(sb + elc * 1152), "r"(1152) : "memory");
            }
            asm volatile("cp.async.bulk.commit_group;" ::: "memory");
        }
    }
    // full drain before exit (R6-proven requirement)
    if (ci == 0) asm volatile("cp.async.bulk.wait_group 0;" ::: "memory");
    __syncwarp();
}

// ---------------------------------------------------------------------------
extern "C" void kernel_launch(void* const* d_in, const int* in_sizes, int n_in,
                              void* d_out, int out_size)
{
    const float* f     = (const float*)d_in[0];
    const float* basis = (const float*)d_in[1];
    const float* w1    = (const float*)d_in[2];
    const float* b1    = (const float*)d_in[3];
    const float* g1    = (const float*)d_in[4];
    const float* be1   = (const float*)d_in[5];
    const float* w2    = (const float*)d_in[6];
    const float* b2    = (const float*)d_in[7];
    const float* g2    = (const float*)d_in[8];
    const float* be2   = (const float*)d_in[9];
    const float* w3    = (const float*)d_in[10];
    const float* b3    = (const float*)d_in[11];
    float* out = (float*)d_out;

    mlp_kernel<<<(E_TOTAL + 31) / 32, 256>>>(f, w1, b1, g1, be1, w2, b2, g2, be2);

    dim3 grid(32, (E_TOTAL + TILE_E - 1) / TILE_E);
    conv_kernel<<<grid, 128>>>(basis, w3, b3, out);
}

// round 11
// speedup vs baseline: 1.4051x; 1.2869x over previous
#include <cuda_runtime.h>

#define E_TOTAL 20000
#define FDIM 17
#define HDIM 32
#define TILE_E 128
#define LN_EPS 1e-5f

__device__ float g_h[E_TOTAL * HDIM];

// ---------- packed fp32x2 helpers (Blackwell dual-FP32) ----------
__device__ __forceinline__ unsigned long long pk2(float x, float y) {
    unsigned long long r;
    asm("mov.b64 %0, {%1, %2};" : "=l"(r) : "f"(x), "f"(y));
    return r;
}
__device__ __forceinline__ void upk2(unsigned long long v, float& x, float& y) {
    asm("mov.b64 {%0, %1}, %2;" : "=f"(x), "=f"(y) : "l"(v));
}
__device__ __forceinline__ void fma2(unsigned long long& d,
                                     unsigned long long a, unsigned long long b) {
    asm("fma.rn.f32x2 %0, %1, %2, %0;" : "+l"(d) : "l"(a), "l"(b));
}

// ---------------------------------------------------------------------------
// Kernel 1: radial MLP  f[E,17] -> h[E,32]   (4 edges per warp)
// ---------------------------------------------------------------------------
__global__ __launch_bounds__(256) void mlp_kernel(
    const float* __restrict__ f,
    const float* __restrict__ w1, const float* __restrict__ b1,
    const float* __restrict__ g1, const float* __restrict__ be1,
    const float* __restrict__ w2, const float* __restrict__ b2,
    const float* __restrict__ g2, const float* __restrict__ be2)
{
    const int tid  = threadIdx.x;
    const int warp = tid >> 5;
    const int lane = tid & 31;

    __shared__ float w1s[32 * FDIM];
    __shared__ float w2s[32 * 33];
    __shared__ float sf[8][FDIM];
    __shared__ float sh[8][HDIM];

    for (int i = tid; i < 32 * FDIM; i += 256) w1s[i] = w1[i];
    for (int i = tid; i < 32 * 32;  i += 256) w2s[(i >> 5) * 33 + (i & 31)] = w2[i];
    __syncthreads();

    const float bb1 = b1[lane], gg1 = g1[lane], bbe1 = be1[lane];
    const float bb2 = b2[lane], gg2 = g2[lane], bbe2 = be2[lane];

    const int ebase = blockIdx.x * 32 + warp * 4;

    #pragma unroll 1
    for (int it = 0; it < 4; it++) {
        const int e = ebase + it;
        if (e >= E_TOTAL) break;

        if (lane < FDIM) sf[warp][lane] = f[e * FDIM + lane];
        __syncwarp();

        float acc = bb1;
        #pragma unroll
        for (int j = 0; j < FDIM; j++)
            acc = fmaf(sf[warp][j], w1s[lane * FDIM + j], acc);

        float m = acc;
        #pragma unroll
        for (int o = 16; o > 0; o >>= 1) m += __shfl_xor_sync(0xffffffffu, m, o);
        m *= (1.0f / 32.0f);
        float d = acc - m;
        float v = d * d;
        #pragma unroll
        for (int o = 16; o > 0; o >>= 1) v += __shfl_xor_sync(0xffffffffu, v, o);
        v *= (1.0f / 32.0f);
        float y = fmaxf(fmaf(d * rsqrtf(v + LN_EPS), gg1, bbe1), 0.0f);

        sh[warp][lane] = y;
        __syncwarp();

        float acc2 = bb2;
        #pragma unroll
        for (int k = 0; k < HDIM; k++)
            acc2 = fmaf(sh[warp][k], w2s[lane * 33 + k], acc2);

        float m2 = acc2;
        #pragma unroll
        for (int o = 16; o > 0; o >>= 1) m2 += __shfl_xor_sync(0xffffffffu, m2, o);
        m2 *= (1.0f / 32.0f);
        float d2 = acc2 - m2;
        float v2 = d2 * d2;
        #pragma unroll
        for (int o = 16; o > 0; o >>= 1) v2 += __shfl_xor_sync(0xffffffffu, v2, o);
        v2 *= (1.0f / 32.0f);
        float y2 = fmaxf(fmaf(d2 * rsqrtf(v2 + LN_EPS), gg2, bbe2), 0.0f);

        g_h[e * HDIM + lane] = y2;
        __syncwarp();
    }
}

// ---------------------------------------------------------------------------
// Kernel 2: fused r = h @ w3^T + b3, einsum with basis, direct write.
// Grid (32 co, 157 tiles); block 128 = 4 warps, lane = ci.
// Main loop: f32x2 FMA with register-resident w3 slice (R5 structure).
// Stores: each thread's 3 floats per row are consecutive (12B @ ci*3).
//   parity-folded STG.64+STG.32 pair per row: 6 store instr (was 9),
//   18 L1 wavefronts (was 27). 3 SELs/row on the idle ALU pipe.
// ---------------------------------------------------------------------------
__global__ __launch_bounds__(128, 4) void conv_kernel(
    const float* __restrict__ basis,
    const float* __restrict__ w3,
    const float* __restrict__ b3,
    float* __restrict__ out)
{
    const int co    = blockIdx.x;
    const int ebase = blockIdx.y * TILE_E;
    const int tid   = threadIdx.x;
    const int ci    = tid & 31;
    const int warp  = tid >> 5;

    __shared__ float w_s[96 * 36];
    __shared__ float h_s[TILE_E * HDIM];
    __shared__ float B_s[TILE_E * 28];

    // --- stage w3 slice for this co (contiguous rows) ---
    {
        const float4* src = (const float4*)(w3 + (size_t)co * 96 * 32);
        #pragma unroll
        for (int g = tid; g < 768; g += 128) {
            int row = g >> 3, qi = g & 7;
            *(float4*)&w_s[row * 36 + qi * 4] = src[g];
        }
    }
    const int nE = (E_TOTAL - ebase < TILE_E) ? (E_TOTAL - ebase) : TILE_E;
    // --- stage h tile ---
    {
        const float4* src = (const float4*)(g_h + (size_t)ebase * HDIM);
        const int nf4 = (nE * HDIM) >> 2;
        for (int g = tid; g < nf4; g += 128)
            *(float4*)&h_s[g * 4] = src[g];
    }
    // --- stage basis tile (27 -> stride 28) ---
    {
        const float* src = basis + (size_t)ebase * 27;
        const int n = nE * 27;
        for (int g = tid; g < n; g += 128) {
            int el = g / 27, j = g - el * 27;
            B_s[el * 28 + j] = src[g];
        }
    }
    __syncthreads();

    // --- per-thread register copy of its 3 w3 rows, packed f32x2 ---
    unsigned long long wpk[3][16];
    #pragma unroll
    for (int ff = 0; ff < 3; ff++) {
        const float* wr = &w_s[(ci * 3 + ff) * 36];
        #pragma unroll
        for (int q = 0; q < 8; q++) {
            float4 t = *(const float4*)&wr[q * 4];
            wpk[ff][2 * q + 0] = pk2(t.x, t.y);
            wpk[ff][2 * q + 1] = pk2(t.z, t.w);
        }
    }
    const int ibase = (co * 32 + ci) * 3;
    const float bias0 = b3[ibase + 0];
    const float bias1 = b3[ibase + 1];
    const float bias2 = b3[ibase + 2];

    const bool evenc = (ci & 1) == 0;
    const int offA = ci & 1;                 // float offset of the 64-bit store
    const int offB = evenc ? 2 : 0;          // float offset of the 32-bit store

    #pragma unroll 1
    for (int el = warp * 32; el < (warp + 1) * 32; el++) {
        if (el >= nE) break;                      // warp-uniform

        unsigned long long a0 = pk2(bias0, 0.0f);
        unsigned long long a1 = pk2(bias1, 0.0f);
        unsigned long long a2 = pk2(bias2, 0.0f);

        const float* hp = &h_s[el * HDIM];
        #pragma unroll
        for (int q = 0; q < 8; q++) {
            float4 hv = *(const float4*)&hp[q * 4];   // LDS.128 broadcast
            unsigned long long h01 = pk2(hv.x, hv.y);
            unsigned long long h23 = pk2(hv.z, hv.w);
            fma2(a0, h01, wpk[0][2 * q]);  fma2(a0, h23, wpk[0][2 * q + 1]);
            fma2(a1, h01, wpk[1][2 * q]);  fma2(a1, h23, wpk[1][2 * q + 1]);
            fma2(a2, h01, wpk[2][2 * q]);  fma2(a2, h23, wpk[2][2 * q + 1]);
        }
        float r0, r0b, r1, r1b, r2, r2b;
        upk2(a0, r0, r0b);  upk2(a1, r1, r1b);  upk2(a2, r2, r2b);
        r0 += r0b;  r1 += r1b;  r2 += r2b;

        // --- streaming epilogue: consume basis float4s immediately ---
        const float4* Bp4 = (const float4*)&B_s[el * 28];
        float o0, o1, o2, o3, o4, o5, o6, o7, o8;
        {
            float4 a = Bp4[0];
            o0 = fmaf(r2, a.z, fmaf(r1, a.y, r0 * a.x));
            o1 = r0 * a.w;
            float4 b = Bp4[1];
            o1 = fmaf(r2, b.y, fmaf(r1, b.x, o1));
            o2 = fmaf(r1, b.w, r0 * b.z);
            float4 c = Bp4[2];
            o2 = fmaf(r2, c.x, o2);
            o3 = fmaf(r2, c.w, fmaf(r1, c.z, r0 * c.y));
            float4 d = Bp4[3];
            o4 = fmaf(r2, d.z, fmaf(r1, d.y, r0 * d.x));
            o5 = r0 * d.w;
            float4 e4 = Bp4[4];
            o5 = fmaf(r2, e4.y, fmaf(r1, e4.x, o5));
            o6 = fmaf(r1, e4.w, r0 * e4.z);
            float4 f4 = Bp4[5];
            o6 = fmaf(r2, f4.x, o6);
            o7 = fmaf(r2, f4.w, fmaf(r1, f4.z, r0 * f4.y));
            float4 g4 = Bp4[6];
            o8 = fmaf(r2, g4.z, fmaf(r1, g4.y, r0 * g4.x));
        }

        float* op = out + (size_t)(ebase + el) * 9216 + (size_t)co * 288 + ci * 3;

        // parity-folded paired stores: even ci -> v2@+0, s@+2 ; odd -> s@+0, v2@+1
        {
            float2 vA;
            vA.x = evenc ? o0 : o1;
            vA.y = evenc ? o1 : o2;
            float vB = evenc ? o2 : o0;
            *(float2*)(op + offA)       = vA;
            op[offB]                    = vB;

            vA.x = evenc ? o3 : o4;
            vA.y = evenc ? o4 : o5;
            vB   = evenc ? o5 : o3;
            *(float2*)(op + 96 + offA)  = vA;
            op[96 + offB]               = vB;

            vA.x = evenc ? o6 : o7;
            vA.y = evenc ? o7 : o8;
            vB   = evenc ? o8 : o6;
            *(float2*)(op + 192 + offA) = vA;
            op[192 + offB]              = vB;
        }
    }
}

// ---------------------------------------------------------------------------
extern "C" void kernel_launch(void* const* d_in, const int* in_sizes, int n_in,
                              void* d_out, int out_size)
{
    const float* f     = (const float*)d_in[0];
    const float* basis = (const float*)d_in[1];
    const float* w1    = (const float*)d_in[2];
    const float* b1    = (const float*)d_in[3];
    const float* g1    = (const float*)d_in[4];
    const float* be1   = (const float*)d_in[5];
    const float* w2    = (const float*)d_in[6];
    const float* b2    = (const float*)d_in[7];
    const float* g2    = (const float*)d_in[8];
    const float* be2   = (const float*)d_in[9];
    const float* w3    = (const float*)d_in[10];
    const float* b3    = (const float*)d_in[11];
    float* out = (float*)d_out;

    mlp_kernel<<<(E_TOTAL + 31) / 32, 256>>>(f, w1, b1, g1, be1, w2, b2, g2, be2);

    dim3 grid(32, (E_TOTAL + TILE_E - 1) / TILE_E);
    conv_kernel<<<grid, 128>>>(basis, w3, b3, out);
}

// round 12
// speedup vs baseline: 1.4879x; 1.0589x over previous
#include <cuda_runtime.h>

#define E_TOTAL 20000
#define FDIM 17
#define HDIM 32
#define TILE_E 128
#define LN_EPS 1e-5f

__device__ float g_h[E_TOTAL * HDIM];

// ---------- packed fp32x2 helpers (Blackwell dual-FP32) ----------
__device__ __forceinline__ unsigned long long pk2(float x, float y) {
    unsigned long long r;
    asm("mov.b64 %0, {%1, %2};" : "=l"(r) : "f"(x), "f"(y));
    return r;
}
__device__ __forceinline__ void upk2(unsigned long long v, float& x, float& y) {
    asm("mov.b64 {%0, %1}, %2;" : "=f"(x), "=f"(y) : "l"(v));
}
__device__ __forceinline__ void fma2(unsigned long long& d,
                                     unsigned long long a, unsigned long long b) {
    asm("fma.rn.f32x2 %0, %1, %2, %0;" : "+l"(d) : "l"(a), "l"(b));
}

// ---------------------------------------------------------------------------
// Kernel 1: radial MLP  f[E,17] -> h[E,32]   (4 edges per warp — R6-proven)
// ---------------------------------------------------------------------------
__global__ __launch_bounds__(256) void mlp_kernel(
    const float* __restrict__ f,
    const float* __restrict__ w1, const float* __restrict__ b1,
    const float* __restrict__ g1, const float* __restrict__ be1,
    const float* __restrict__ w2, const float* __restrict__ b2,
    const float* __restrict__ g2, const float* __restrict__ be2)
{
    const int tid  = threadIdx.x;
    const int warp = tid >> 5;
    const int lane = tid & 31;

    __shared__ float w1s[32 * FDIM];      // 17 odd => conflict-free
    __shared__ float w2s[32 * 33];        // padded
    __shared__ float sf[8][FDIM];
    __shared__ float sh[8][HDIM];

    for (int i = tid; i < 32 * FDIM; i += 256) w1s[i] = w1[i];
    for (int i = tid; i < 32 * 32;  i += 256) w2s[(i >> 5) * 33 + (i & 31)] = w2[i];
    __syncthreads();

    const float bb1 = b1[lane], gg1 = g1[lane], bbe1 = be1[lane];
    const float bb2 = b2[lane], gg2 = g2[lane], bbe2 = be2[lane];

    const int ebase = blockIdx.x * 32 + warp * 4;

    #pragma unroll 1
    for (int it = 0; it < 4; it++) {
        const int e = ebase + it;
        if (e >= E_TOTAL) break;

        if (lane < FDIM) sf[warp][lane] = f[e * FDIM + lane];
        __syncwarp();

        float acc = bb1;
        #pragma unroll
        for (int j = 0; j < FDIM; j++)
            acc = fmaf(sf[warp][j], w1s[lane * FDIM + j], acc);

        float m = acc;
        #pragma unroll
        for (int o = 16; o > 0; o >>= 1) m += __shfl_xor_sync(0xffffffffu, m, o);
        m *= (1.0f / 32.0f);
        float d = acc - m;
        float v = d * d;
        #pragma unroll
        for (int o = 16; o > 0; o >>= 1) v += __shfl_xor_sync(0xffffffffu, v, o);
        v *= (1.0f / 32.0f);
        float y = fmaxf(fmaf(d * rsqrtf(v + LN_EPS), gg1, bbe1), 0.0f);

        sh[warp][lane] = y;
        __syncwarp();

        float acc2 = bb2;
        #pragma unroll
        for (int k = 0; k < HDIM; k++)
            acc2 = fmaf(sh[warp][k], w2s[lane * 33 + k], acc2);

        float m2 = acc2;
        #pragma unroll
        for (int o = 16; o > 0; o >>= 1) m2 += __shfl_xor_sync(0xffffffffu, m2, o);
        m2 *= (1.0f / 32.0f);
        float d2 = acc2 - m2;
        float v2 = d2 * d2;
        #pragma unroll
        for (int o = 16; o > 0; o >>= 1) v2 += __shfl_xor_sync(0xffffffffu, v2, o);
        v2 *= (1.0f / 32.0f);
        float y2 = fmaxf(fmaf(d2 * rsqrtf(v2 + LN_EPS), gg2, bbe2), 0.0f);

        g_h[e * HDIM + lane] = y2;
        __syncwarp();
    }
}

// ---------------------------------------------------------------------------
// Kernel 2: fused r = h @ w3^T + b3, einsum with basis, direct write.
// R5-proven structure. Micro-opts: h loaded as ulonglong2 (LDS.128 lands in
// aligned b64 pairs, no repacking MOVs); biases packed once outside the loop.
// ---------------------------------------------------------------------------
__global__ __launch_bounds__(128, 4) void conv_kernel(
    const float* __restrict__ basis,
    const float* __restrict__ w3,
    const float* __restrict__ b3,
    float* __restrict__ out)
{
    const int co    = blockIdx.x;
    const int ebase = blockIdx.y * TILE_E;
    const int tid   = threadIdx.x;
    const int ci    = tid & 31;
    const int warp  = tid >> 5;

    __shared__ float w_s[96 * 36];
    __shared__ float h_s[TILE_E * HDIM];
    __shared__ float B_s[TILE_E * 28];      // stride 28 (112B, 16B-aligned rows)

    // --- stage w3 slice for this co (contiguous rows) ---
    {
        const float4* src = (const float4*)(w3 + (size_t)co * 96 * 32);
        #pragma unroll
        for (int g = tid; g < 768; g += 128) {
            int row = g >> 3, qi = g & 7;
            *(float4*)&w_s[row * 36 + qi * 4] = src[g];
        }
    }
    const int nE = (E_TOTAL - ebase < TILE_E) ? (E_TOTAL - ebase) : TILE_E;
    // --- stage h tile ---
    {
        const float4* src = (const float4*)(g_h + (size_t)ebase * HDIM);
        const int nf4 = (nE * HDIM) >> 2;
        for (int g = tid; g < nf4; g += 128)
            *(float4*)&h_s[g * 4] = src[g];
    }
    // --- stage basis tile (27 -> stride 28) ---
    {
        const float* src = basis + (size_t)ebase * 27;
        const int n = nE * 27;
        for (int g = tid; g < n; g += 128) {
            int el = g / 27, j = g - el * 27;
            B_s[el * 28 + j] = src[g];
        }
    }
    __syncthreads();

    // --- per-thread register copy of its 3 w3 rows, packed f32x2 ---
    unsigned long long wpk[3][16];
    #pragma unroll
    for (int ff = 0; ff < 3; ff++) {
        const float* wr = &w_s[(ci * 3 + ff) * 36];
        #pragma unroll
        for (int q = 0; q < 8; q++) {
            float4 t = *(const float4*)&wr[q * 4];
            wpk[ff][2 * q + 0] = pk2(t.x, t.y);
            wpk[ff][2 * q + 1] = pk2(t.z, t.w);
        }
    }
    const int ibase = (co * 32 + ci) * 3;
    const unsigned long long bias0p = pk2(b3[ibase + 0], 0.0f);
    const unsigned long long bias1p = pk2(b3[ibase + 1], 0.0f);
    const unsigned long long bias2p = pk2(b3[ibase + 2], 0.0f);

    #pragma unroll 1
    for (int el = warp * 32; el < (warp + 1) * 32; el++) {
        if (el >= nE) break;                      // warp-uniform

        unsigned long long a0 = bias0p;
        unsigned long long a1 = bias1p;
        unsigned long long a2 = bias2p;

        const ulonglong2* hp = (const ulonglong2*)&h_s[el * HDIM];
        #pragma unroll
        for (int q = 0; q < 8; q++) {
            ulonglong2 hv = hp[q];                // LDS.128 -> two b64 pairs
            fma2(a0, hv.x, wpk[0][2 * q]);  fma2(a0, hv.y, wpk[0][2 * q + 1]);
            fma2(a1, hv.x, wpk[1][2 * q]);  fma2(a1, hv.y, wpk[1][2 * q + 1]);
            fma2(a2, hv.x, wpk[2][2 * q]);  fma2(a2, hv.y, wpk[2][2 * q + 1]);
        }
        float r0, r0b, r1, r1b, r2, r2b;
        upk2(a0, r0, r0b);  upk2(a1, r1, r1b);  upk2(a2, r2, r2b);
        r0 += r0b;  r1 += r1b;  r2 += r2b;

        // --- streaming epilogue: consume basis float4s immediately ---
        const float4* Bp4 = (const float4*)&B_s[el * 28];
        float o0, o1, o2, o3, o4, o5, o6, o7, o8;
        {
            float4 a = Bp4[0];                                  // m 0..3
            o0 = fmaf(r2, a.z, fmaf(r1, a.y, r0 * a.x));
            o1 = r0 * a.w;
            float4 b = Bp4[1];                                  // m 4..7
            o1 = fmaf(r2, b.y, fmaf(r1, b.x, o1));
            o2 = fmaf(r1, b.w, r0 * b.z);
            float4 c = Bp4[2];                                  // m 8..11
            o2 = fmaf(r2, c.x, o2);
            o3 = fmaf(r2, c.w, fmaf(r1, c.z, r0 * c.y));
            float4 d = Bp4[3];                                  // m 12..15
            o4 = fmaf(r2, d.z, fmaf(r1, d.y, r0 * d.x));
            o5 = r0 * d.w;
            float4 e4 = Bp4[4];                                 // m 16..19
            o5 = fmaf(r2, e4.y, fmaf(r1, e4.x, o5));
            o6 = fmaf(r1, e4.w, r0 * e4.z);
            float4 f4 = Bp4[5];                                 // m 20..23
            o6 = fmaf(r2, f4.x, o6);
            o7 = fmaf(r2, f4.w, fmaf(r1, f4.z, r0 * f4.y));
            float4 g4 = Bp4[6];                                 // m 24..26 (+pad)
            o8 = fmaf(r2, g4.z, fmaf(r1, g4.y, r0 * g4.x));
        }

        float* op = out + (size_t)(ebase + el) * 9216 + (size_t)(co * 3) * 96 + ci * 3;
        op[0]   = o0;  op[1]   = o1;  op[2]   = o2;
        op[96]  = o3;  op[97]  = o4;  op[98]  = o5;
        op[192] = o6;  op[193] = o7;  op[194] = o8;
    }
}

// ---------------------------------------------------------------------------
extern "C" void kernel_launch(void* const* d_in, const int* in_sizes, int n_in,
                              void* d_out, int out_size)
{
    const float* f     = (const float*)d_in[0];
    const float* basis = (const float*)d_in[1];
    const float* w1    = (const float*)d_in[2];
    const float* b1    = (const float*)d_in[3];
    const float* g1    = (const float*)d_in[4];
    const float* be1   = (const float*)d_in[5];
    const float* w2    = (const float*)d_in[6];
    const float* b2    = (const float*)d_in[7];
    const float* g2    = (const float*)d_in[8];
    const float* be2   = (const float*)d_in[9];
    const float* w3    = (const float*)d_in[10];
    const float* b3    = (const float*)d_in[11];
    float* out = (float*)d_out;

    mlp_kernel<<<(E_TOTAL + 31) / 32, 256>>>(f, w1, b1, g1, be1, w2, b2, g2, be2);

    dim3 grid(32, (E_TOTAL + TILE_E - 1) / TILE_E);
    conv_kernel<<<grid, 128>>>(basis, w3, b3, out);
}